// round 7
// baseline (speedup 1.0000x reference)
#include <cuda_runtime.h>
#include <cuda_bf16.h>
#include <cstdint>
#include <math.h>

#define NROW    16384
#define KNBR    16
#define IN_DIM  256
#define HID_DIM 512
#define LN_EPS  1e-5f

// ---------------------------------------------------------------------------
// Low-level helpers (baseline sm_80+ instructions: valid on compute_103)
// ---------------------------------------------------------------------------
__device__ __forceinline__ uint32_t smem_u32(const void* p) {
    uint32_t a;
    asm("{ .reg .u64 t; cvta.to.shared.u64 t, %1; cvt.u32.u64 %0, t; }"
        : "=r"(a) : "l"(p));
    return a;
}
__device__ __forceinline__ void cpasync16(uint32_t dst, const void* src) {
    asm volatile("cp.async.cg.shared.global [%0], [%1], 16;" :: "r"(dst), "l"(src));
}
#define CP_COMMIT() asm volatile("cp.async.commit_group;" ::: "memory")
#define CP_WAIT(n)  asm volatile("cp.async.wait_group %0;" :: "n"(n) : "memory")

__device__ __forceinline__ void ldsm4(uint32_t* r, uint32_t addr) {
    asm volatile("ldmatrix.sync.aligned.m8n8.x4.shared.b16 {%0,%1,%2,%3}, [%4];"
        : "=r"(r[0]), "=r"(r[1]), "=r"(r[2]), "=r"(r[3]) : "r"(addr));
}
__device__ __forceinline__ void mma16816(float* d, const uint32_t* a, const uint32_t* b) {
    asm volatile("mma.sync.aligned.m16n8k16.row.col.f32.bf16.bf16.f32 "
        "{%0,%1,%2,%3}, {%4,%5,%6,%7}, {%8,%9}, {%0,%1,%2,%3};"
        : "+f"(d[0]), "+f"(d[1]), "+f"(d[2]), "+f"(d[3])
        : "r"(a[0]), "r"(a[1]), "r"(a[2]), "r"(a[3]), "r"(b[0]), "r"(b[1]));
}
__device__ __forceinline__ int swz(int off) { return off ^ ((off >> 3) & 0x70); }

// Pack two floats into bf16x2 hi word; emit bf16x2 lo word (split residual).
__device__ __forceinline__ uint32_t pack_split(float a, float b, uint32_t& lo) {
    __nv_bfloat16 ha = __float2bfloat16(a), hb = __float2bfloat16(b);
    float la = a - __bfloat162float(ha);
    float lb = b - __bfloat162float(hb);
    lo = ((uint32_t)__bfloat16_as_ushort(__float2bfloat16(lb)) << 16) |
         (uint32_t)__bfloat16_as_ushort(__float2bfloat16(la));
    return ((uint32_t)__bfloat16_as_ushort(hb) << 16) |
           (uint32_t)__bfloat16_as_ushort(ha);
}

// ---------------------------------------------------------------------------
// Scratch (device globals; no allocation allowed)
// ---------------------------------------------------------------------------
__device__ __nv_bfloat16 g_data_h[NROW * IN_DIM],  g_data_l[NROW * IN_DIM];
__device__ __nv_bfloat16 g_h1_h  [NROW * HID_DIM], g_h1_l  [NROW * HID_DIM];
__device__ __nv_bfloat16 g_h2_h  [NROW * HID_DIM], g_h2_l  [NROW * HID_DIM];
__device__ __nv_bfloat16 g_loc_h [NROW * HID_DIM], g_loc_l [NROW * HID_DIM];
__device__ __nv_bfloat16 g_at_h  [NROW * HID_DIM], g_at_l  [NROW * HID_DIM];
__device__ float g_h3   [NROW * HID_DIM];
__device__ float g_pd   [NROW * HID_DIM];
__device__ float g_q    [NROW * HID_DIM];
__device__ float g_k    [NROW * HID_DIM];
__device__ float g_v    [NROW * HID_DIM];
__device__ float g_inter[NROW * HID_DIM];
__device__ float g_pi   [NROW * HID_DIM];
// transposed + split weights: [N=512][K]
__device__ __nv_bfloat16 g_w0t_h[512 * 256], g_w0t_l[512 * 256];
__device__ __nv_bfloat16 g_w1t_h[512 * 512], g_w1t_l[512 * 512];
__device__ __nv_bfloat16 g_w2t_h[512 * 512], g_w2t_l[512 * 512];
__device__ __nv_bfloat16 g_pdt_h[512 * 256], g_pdt_l[512 * 256];
__device__ __nv_bfloat16 g_pit_h[512 * 256], g_pit_l[512 * 256];
__device__ __nv_bfloat16 g_qt_h [512 * 512], g_qt_l [512 * 512];
__device__ __nv_bfloat16 g_kt_h [512 * 512], g_kt_l [512 * 512];
__device__ __nv_bfloat16 g_vt_h [512 * 512], g_vt_l [512 * 512];
__device__ __nv_bfloat16 g_ot_h [512 * 512], g_ot_l [512 * 512];

// ---------------------------------------------------------------------------
// Batched weight transpose + bf16 split (all 9 weights in one launch).
// ---------------------------------------------------------------------------
struct WJob { const float* W; __nv_bfloat16* Th; __nv_bfloat16* Tl; int K; };
struct WJobs { WJob j[9]; };

__global__ void wsplit_all(WJobs jobs) {
    __shared__ float tile[32][33];
    const WJob jb = jobs.j[blockIdx.z];
    const int n0 = blockIdx.x * 32, k0 = blockIdx.y * 32;
    if (k0 >= jb.K) return;
    for (int i = threadIdx.y; i < 32; i += 8)
        tile[i][threadIdx.x] = jb.W[(size_t)(k0 + i) * 512 + n0 + threadIdx.x];
    __syncthreads();
    for (int i = threadIdx.y; i < 32; i += 8) {
        float x = tile[threadIdx.x][i];
        __nv_bfloat16 h = __float2bfloat16(x);
        jb.Th[(size_t)(n0 + i) * jb.K + k0 + threadIdx.x] = h;
        jb.Tl[(size_t)(n0 + i) * jb.K + k0 + threadIdx.x] =
            __float2bfloat16(x - __bfloat162float(h));
    }
}

// fp32 -> bf16 hi/lo split (vectorized, 8 elems/thread)
__global__ void split_f32(const float* __restrict__ x, __nv_bfloat16* __restrict__ h,
                          __nv_bfloat16* __restrict__ l, int n) {
    int i = (blockIdx.x * 256 + threadIdx.x) * 8;
    if (i >= n) return;
    float4 a = *(const float4*)(x + i);
    float4 b = *(const float4*)(x + i + 4);
    float xs[8] = {a.x, a.y, a.z, a.w, b.x, b.y, b.z, b.w};
    uint32_t ph[4], pl[4];
#pragma unroll
    for (int j = 0; j < 4; j++) ph[j] = pack_split(xs[2 * j], xs[2 * j + 1], pl[j]);
    *(uint4*)(h + i) = make_uint4(ph[0], ph[1], ph[2], ph[3]);
    *(uint4*)(l + i) = make_uint4(pl[0], pl[1], pl[2], pl[3]);
}

// ---------------------------------------------------------------------------
// HMMA GEMM: C[M,512] = act(A[M,K] @ W[K,512] + bias)
// A as bf16 hi/lo pair [M,K]; W transposed+split as [512][K] (col-major B).
// 3 MMA passes per k-chunk: Ahi*Bhi + Ahi*Blo + Alo*Bhi (fp32 accum).
// BM=BN=128, BK=64, 3-stage cp.async pipeline, 512 threads (16 warps 4x4),
// warp tile 32x32.
// ---------------------------------------------------------------------------
#define STAGE_BYTES 65536
#define GEMM_SMEM   (3 * STAGE_BYTES)

template <int ACT, int WF32, int WPAIR>
__global__ void __launch_bounds__(512, 1)
gemm_hmma(const __nv_bfloat16* __restrict__ Ah, const __nv_bfloat16* __restrict__ Al,
          const __nv_bfloat16* __restrict__ Bh, const __nv_bfloat16* __restrict__ Bl,
          const float* __restrict__ bias, float* __restrict__ Cf,
          __nv_bfloat16* __restrict__ Ch, __nv_bfloat16* __restrict__ Cl, int Ktot) {
    extern __shared__ __align__(1024) char smem[];
    const uint32_t sb = smem_u32(smem);
    const int tid = threadIdx.x, wid = tid >> 5, lane = tid & 31;
    const int warp_m = wid & 3, warp_n = wid >> 2;   // 4 x 4
    const int bm = blockIdx.y * 128, bn = blockIdx.x * 128;

    const __nv_bfloat16* a0 = Ah + (size_t)bm * Ktot;
    const __nv_bfloat16* a1 = Al + (size_t)bm * Ktot;
    const __nv_bfloat16* b0 = Bh + (size_t)bn * Ktot;
    const __nv_bfloat16* b1 = Bl + (size_t)bn * Ktot;

    float acc[2][4][4];
#pragma unroll
    for (int a = 0; a < 2; a++)
#pragma unroll
        for (int b = 0; b < 4; b++)
#pragma unroll
            for (int c = 0; c < 4; c++) acc[a][b][c] = 0.f;

    // ldmatrix per-thread base addressing
    const int a_row = warp_m * 32 + (lane & 15);                          // + mt*16
    const int a_kb  = ((lane >> 4) & 1) * 16;                             // bytes
    const int b_row = warp_n * 32 + ((lane >> 4) & 1) * 8 + (lane & 7);   // + nt2*16
    const int b_kb  = ((lane >> 3) & 1) * 16;                             // bytes

    const int S = Ktot >> 6;

    auto load_stage = [&](int buf, int k0) {
        const uint32_t st = sb + buf * STAGE_BYTES;
#pragma unroll
        for (int i = 0; i < 2; i++) {
            const int c   = tid + (i << 9);        // 0..1023
            const int row = c >> 3, kc = c & 7;
            const size_t go = (size_t)row * Ktot + k0 + kc * 8;
            const int so = swz(row * 128 + kc * 16);
            cpasync16(st + so,         a0 + go);
            cpasync16(st + 16384 + so, a1 + go);
            cpasync16(st + 32768 + so, b0 + go);
            cpasync16(st + 49152 + so, b1 + go);
        }
    };

    load_stage(0, 0);
    CP_COMMIT();
    if (S > 1) { load_stage(1, 64); CP_COMMIT(); }

    for (int s = 0; s < S; s++) {
        if (s + 2 < S) { CP_WAIT(1); } else { CP_WAIT(0); }
        __syncthreads();
        if (s + 2 < S) { load_stage((s + 2) % 3, (s + 2) << 6); CP_COMMIT(); }

        const uint32_t tb = sb + (s % 3) * STAGE_BYTES;
#pragma unroll
        for (int kk = 0; kk < 4; kk++) {
            uint32_t ah[8], al[8], bh[8], bl[8];
#pragma unroll
            for (int mt = 0; mt < 2; mt++) {
                const int off = swz((a_row + mt * 16) * 128 + kk * 32 + a_kb);
                ldsm4(ah + 4 * mt, tb + off);
                ldsm4(al + 4 * mt, tb + 16384 + off);
            }
#pragma unroll
            for (int nt2 = 0; nt2 < 2; nt2++) {
                const int off = swz((b_row + nt2 * 16) * 128 + kk * 32 + b_kb);
                ldsm4(bh + 4 * nt2, tb + 32768 + off);
                ldsm4(bl + 4 * nt2, tb + 49152 + off);
            }
#pragma unroll
            for (int mt = 0; mt < 2; mt++)
#pragma unroll
                for (int nt = 0; nt < 4; nt++) {
                    mma16816(acc[mt][nt], ah + 4 * mt, bh + nt * 2);
                    mma16816(acc[mt][nt], ah + 4 * mt, bl + nt * 2);
                    mma16816(acc[mt][nt], al + 4 * mt, bh + nt * 2);
                }
        }
        __syncthreads();
    }

    // ---- epilogue: bias + act + store (fp32 and/or bf16 hi/lo pair) ----
    const int col_base = bn + warp_n * 32 + (lane & 3) * 2;
    const int row_base = bm + warp_m * 32 + (lane >> 2);
#pragma unroll
    for (int nt = 0; nt < 4; nt++) {
        const int col = col_base + nt * 8;
        const float2 bv = *(const float2*)&bias[col];
#pragma unroll
        for (int mt = 0; mt < 2; mt++) {
#pragma unroll
            for (int half = 0; half < 2; half++) {
                const int row = row_base + mt * 16 + half * 8;
                float v0 = acc[mt][nt][half * 2 + 0] + bv.x;
                float v1 = acc[mt][nt][half * 2 + 1] + bv.y;
                if (ACT) {
                    v0 = v0 > 0.f ? v0 : expm1f(v0);
                    v1 = v1 > 0.f ? v1 : expm1f(v1);
                }
                if (WF32)
                    *(float2*)(Cf + (size_t)row * 512 + col) = make_float2(v0, v1);
                if (WPAIR) {
                    uint32_t lo, hi = pack_split(v0, v1, lo);
                    *(uint32_t*)(Ch + (size_t)row * 512 + col) = hi;
                    *(uint32_t*)(Cl + (size_t)row * 512 + col) = lo;
                }
            }
        }
    }
}

// ---------------------------------------------------------------------------
// Fused residual + LayerNorm (+ optional ELU). OUT: fp32 or bf16 hi/lo pair.
// ---------------------------------------------------------------------------
template <int ACT, int PAIR>
__global__ void __launch_bounds__(256)
ln_res(const float* __restrict__ a, const float* __restrict__ rr, float rscale,
       const float* __restrict__ g, const float* __restrict__ b,
       float* __restrict__ of, __nv_bfloat16* __restrict__ oh,
       __nv_bfloat16* __restrict__ ol) {
    __shared__ float red[8];
    const int row = blockIdx.x, t = threadIdx.x;
    const float* ap = a  + (size_t)row * 512;
    const float* rp = rr + (size_t)row * 512;

    float x0 = ap[t]       + rscale * rp[t];
    float x1 = ap[t + 256] + rscale * rp[t + 256];

    float s = x0 + x1;
#pragma unroll
    for (int o = 16; o > 0; o >>= 1) s += __shfl_xor_sync(0xffffffffu, s, o);
    if ((t & 31) == 0) red[t >> 5] = s;
    __syncthreads();
    float mean = 0.f;
#pragma unroll
    for (int w = 0; w < 8; w++) mean += red[w];
    mean *= (1.0f / 512.0f);
    __syncthreads();

    float d0 = x0 - mean, d1 = x1 - mean;
    float vs = d0 * d0 + d1 * d1;
#pragma unroll
    for (int o = 16; o > 0; o >>= 1) vs += __shfl_xor_sync(0xffffffffu, vs, o);
    if ((t & 31) == 0) red[t >> 5] = vs;
    __syncthreads();
    float var = 0.f;
#pragma unroll
    for (int w = 0; w < 8; w++) var += red[w];
    var *= (1.0f / 512.0f);

    const float inv = rsqrtf(var + LN_EPS);
    float y0 = d0 * inv * g[t]       + b[t];
    float y1 = d1 * inv * g[t + 256] + b[t + 256];
    if (ACT) {
        y0 = y0 > 0.f ? y0 : expm1f(y0);
        y1 = y1 > 0.f ? y1 : expm1f(y1);
    }
    if (PAIR) {
        __nv_bfloat16 h0 = __float2bfloat16(y0), h1 = __float2bfloat16(y1);
        oh[(size_t)row * 512 + t]       = h0;
        oh[(size_t)row * 512 + t + 256] = h1;
        ol[(size_t)row * 512 + t]       = __float2bfloat16(y0 - __bfloat162float(h0));
        ol[(size_t)row * 512 + t + 256] = __float2bfloat16(y1 - __bfloat162float(h1));
    } else {
        of[(size_t)row * 512 + t]       = y0;
        of[(size_t)row * 512 + t + 256] = y1;
    }
}

// ---------------------------------------------------------------------------
// Neighbor attention (one warp per node). Emits bf16 hi/lo pair for o-GEMM.
// ---------------------------------------------------------------------------
__global__ void __launch_bounds__(256)
nbr_attn(const float* __restrict__ q, const float* __restrict__ kc,
         const float* __restrict__ vc, const int* __restrict__ nbrs,
         __nv_bfloat16* __restrict__ oh, __nv_bfloat16* __restrict__ ol) {
    const int warp = threadIdx.x >> 5;
    const int lane = threadIdx.x & 31;
    const int node = blockIdx.x * 8 + warp;

    const size_t base = (size_t)node * 512 + lane * 16;
    float qr[16];
#pragma unroll
    for (int i = 0; i < 16; i += 4) {
        float4 t = *reinterpret_cast<const float4*>(q + base + i);
        qr[i] = t.x; qr[i + 1] = t.y; qr[i + 2] = t.z; qr[i + 3] = t.w;
    }

    float m = -1e30f, s = 0.f;
    float acc[16];
#pragma unroll
    for (int i = 0; i < 16; i++) acc[i] = 0.f;

#pragma unroll
    for (int j = 0; j < KNBR; j++) {
        const int nb = __ldg(&nbrs[node * KNBR + j]);
        const float* kp = kc + (size_t)nb * 512 + lane * 16;
        const float* vp = vc + (size_t)nb * 512 + lane * 16;

        float dot = 0.f;
        float vr[16];
#pragma unroll
        for (int i = 0; i < 16; i += 4) {
            float4 kv = *reinterpret_cast<const float4*>(kp + i);
            float4 vv = *reinterpret_cast<const float4*>(vp + i);
            dot = fmaf(kv.x, qr[i],     dot);
            dot = fmaf(kv.y, qr[i + 1], dot);
            dot = fmaf(kv.z, qr[i + 2], dot);
            dot = fmaf(kv.w, qr[i + 3], dot);
            vr[i] = vv.x; vr[i + 1] = vv.y; vr[i + 2] = vv.z; vr[i + 3] = vv.w;
        }
        dot += __shfl_xor_sync(0xffffffffu, dot, 1);
        dot += __shfl_xor_sync(0xffffffffu, dot, 2);
        const float score = dot * 0.125f;

        const float mn   = fmaxf(m, score);
        const float corr = __expf(m - mn);
        const float p    = __expf(score - mn);
        s = s * corr + p;
#pragma unroll
        for (int i = 0; i < 16; i++) acc[i] = acc[i] * corr + p * vr[i];
        m = mn;
    }

    const float inv = 1.f / s;
    uint32_t ph[8], pl[8];
#pragma unroll
    for (int j = 0; j < 8; j++)
        ph[j] = pack_split(acc[2 * j] * inv, acc[2 * j + 1] * inv, pl[j]);
    *(uint4*)(oh + base)     = make_uint4(ph[0], ph[1], ph[2], ph[3]);
    *(uint4*)(oh + base + 8) = make_uint4(ph[4], ph[5], ph[6], ph[7]);
    *(uint4*)(ol + base)     = make_uint4(pl[0], pl[1], pl[2], pl[3]);
    *(uint4*)(ol + base + 8) = make_uint4(pl[4], pl[5], pl[6], pl[7]);
}

// ---------------------------------------------------------------------------
// Launch
// ---------------------------------------------------------------------------
extern "C" void kernel_launch(void* const* d_in, const int* in_sizes, int n_in,
                              void* d_out, int out_size) {
    (void)in_sizes; (void)n_in; (void)out_size;
    const float* data   = (const float*)d_in[0];
    const int*   nbrs   = (const int*)  d_in[1];
    const float* mlp_w0 = (const float*)d_in[2];
    const float* mlp_b0 = (const float*)d_in[3];
    const float* mlp_w1 = (const float*)d_in[4];
    const float* mlp_b1 = (const float*)d_in[5];
    const float* mlp_w2 = (const float*)d_in[6];
    const float* mlp_b2 = (const float*)d_in[7];
    const float* pd_w   = (const float*)d_in[8];
    const float* pd_b   = (const float*)d_in[9];
    const float* pi_w   = (const float*)d_in[10];
    const float* pi_b   = (const float*)d_in[11];
    const float* q_w    = (const float*)d_in[12];
    const float* q_b    = (const float*)d_in[13];
    const float* k_w    = (const float*)d_in[14];
    const float* k_b    = (const float*)d_in[15];
    const float* v_w    = (const float*)d_in[16];
    const float* v_b    = (const float*)d_in[17];
    const float* o_w    = (const float*)d_in[18];
    const float* o_b    = (const float*)d_in[19];
    const float* ln1_g  = (const float*)d_in[20];
    const float* ln1_b  = (const float*)d_in[21];
    const float* ln2_g  = (const float*)d_in[22];
    const float* ln2_b  = (const float*)d_in[23];
    float* out = (float*)d_out;

    __nv_bfloat16 *data_h, *data_l, *h1_h, *h1_l, *h2_h, *h2_l, *loc_h, *loc_l, *at_h, *at_l;
    float *h3, *pd, *qb, *kb, *vb, *inter, *pi;
    __nv_bfloat16 *w0h, *w0l, *w1h, *w1l, *w2h, *w2l, *pdh, *pdl, *pih, *pil;
    __nv_bfloat16 *qth, *qtl, *kth, *ktl, *vth, *vtl, *oth, *otl;
    cudaGetSymbolAddress((void**)&data_h, g_data_h); cudaGetSymbolAddress((void**)&data_l, g_data_l);
    cudaGetSymbolAddress((void**)&h1_h, g_h1_h);     cudaGetSymbolAddress((void**)&h1_l, g_h1_l);
    cudaGetSymbolAddress((void**)&h2_h, g_h2_h);     cudaGetSymbolAddress((void**)&h2_l, g_h2_l);
    cudaGetSymbolAddress((void**)&loc_h, g_loc_h);   cudaGetSymbolAddress((void**)&loc_l, g_loc_l);
    cudaGetSymbolAddress((void**)&at_h, g_at_h);     cudaGetSymbolAddress((void**)&at_l, g_at_l);
    cudaGetSymbolAddress((void**)&h3, g_h3);         cudaGetSymbolAddress((void**)&pd, g_pd);
    cudaGetSymbolAddress((void**)&qb, g_q);          cudaGetSymbolAddress((void**)&kb, g_k);
    cudaGetSymbolAddress((void**)&vb, g_v);          cudaGetSymbolAddress((void**)&inter, g_inter);
    cudaGetSymbolAddress((void**)&pi, g_pi);
    cudaGetSymbolAddress((void**)&w0h, g_w0t_h); cudaGetSymbolAddress((void**)&w0l, g_w0t_l);
    cudaGetSymbolAddress((void**)&w1h, g_w1t_h); cudaGetSymbolAddress((void**)&w1l, g_w1t_l);
    cudaGetSymbolAddress((void**)&w2h, g_w2t_h); cudaGetSymbolAddress((void**)&w2l, g_w2t_l);
    cudaGetSymbolAddress((void**)&pdh, g_pdt_h); cudaGetSymbolAddress((void**)&pdl, g_pdt_l);
    cudaGetSymbolAddress((void**)&pih, g_pit_h); cudaGetSymbolAddress((void**)&pil, g_pit_l);
    cudaGetSymbolAddress((void**)&qth, g_qt_h);  cudaGetSymbolAddress((void**)&qtl, g_qt_l);
    cudaGetSymbolAddress((void**)&kth, g_kt_h);  cudaGetSymbolAddress((void**)&ktl, g_kt_l);
    cudaGetSymbolAddress((void**)&vth, g_vt_h);  cudaGetSymbolAddress((void**)&vtl, g_vt_l);
    cudaGetSymbolAddress((void**)&oth, g_ot_h);  cudaGetSymbolAddress((void**)&otl, g_ot_l);

    cudaFuncSetAttribute(gemm_hmma<1, 0, 1>, cudaFuncAttributeMaxDynamicSharedMemorySize, GEMM_SMEM);
    cudaFuncSetAttribute(gemm_hmma<0, 1, 0>, cudaFuncAttributeMaxDynamicSharedMemorySize, GEMM_SMEM);

    WJobs jobs;
    jobs.j[0] = {mlp_w0, w0h, w0l, 256};
    jobs.j[1] = {mlp_w1, w1h, w1l, 512};
    jobs.j[2] = {mlp_w2, w2h, w2l, 512};
    jobs.j[3] = {pd_w,   pdh, pdl, 256};
    jobs.j[4] = {pi_w,   pih, pil, 256};
    jobs.j[5] = {q_w,    qth, qtl, 512};
    jobs.j[6] = {k_w,    kth, ktl, 512};
    jobs.j[7] = {v_w,    vth, vtl, 512};
    jobs.j[8] = {o_w,    oth, otl, 512};

    const dim3 gg(4, 128);

    // 0: all weight transposes
    wsplit_all<<<dim3(16, 16, 9), dim3(32, 8)>>>(jobs);
    // 1: data split
    split_f32<<<(NROW * IN_DIM) / (256 * 8), 256>>>(data, data_h, data_l, NROW * IN_DIM);
    // 2..5: GEMMs (profiler sample lands on one of these)
    gemm_hmma<1, 0, 1><<<gg, 512, GEMM_SMEM>>>(data_h, data_l, w0h, w0l, mlp_b0, nullptr, h1_h, h1_l, 256);
    gemm_hmma<1, 0, 1><<<gg, 512, GEMM_SMEM>>>(h1_h, h1_l,   w1h, w1l, mlp_b1, nullptr, h2_h, h2_l, 512);
    gemm_hmma<0, 1, 0><<<gg, 512, GEMM_SMEM>>>(h2_h, h2_l,   w2h, w2l, mlp_b2, h3, nullptr, nullptr, 512);
    gemm_hmma<0, 1, 0><<<gg, 512, GEMM_SMEM>>>(data_h, data_l, pdh, pdl, pd_b, pd, nullptr, nullptr, 256);
    // 6: local = elu(LN(h3 + 2*pd)) -> bf16 pair
    ln_res<1, 1><<<NROW, 256>>>(h3, pd, 2.0f, ln1_g, ln1_b, nullptr, loc_h, loc_l);
    // 7-9: Q, K, V projections (fp32 outputs for attention)
    gemm_hmma<0, 1, 0><<<gg, 512, GEMM_SMEM>>>(loc_h, loc_l, qth, qtl, q_b, qb, nullptr, nullptr, 512);
    gemm_hmma<0, 1, 0><<<gg, 512, GEMM_SMEM>>>(loc_h, loc_l, kth, ktl, k_b, kb, nullptr, nullptr, 512);
    gemm_hmma<0, 1, 0><<<gg, 512, GEMM_SMEM>>>(loc_h, loc_l, vth, vtl, v_b, vb, nullptr, nullptr, 512);
    // 10: neighbor attention -> bf16 pair
    nbr_attn<<<NROW / 8, 256>>>(qb, kb, vb, nbrs, at_h, at_l);
    // 11-12: output projection + project_in
    gemm_hmma<0, 1, 0><<<gg, 512, GEMM_SMEM>>>(at_h, at_l, oth, otl, o_b, inter, nullptr, nullptr, 512);
    gemm_hmma<0, 1, 0><<<gg, 512, GEMM_SMEM>>>(data_h, data_l, pih, pil, pi_b, pi, nullptr, nullptr, 256);
    // 13: out = LN(inter + pi)
    ln_res<0, 0><<<NROW, 256>>>(inter, pi, 1.0f, ln2_g, ln2_b, out, nullptr, nullptr);
}

// round 8
// speedup vs baseline: 1.2290x; 1.2290x over previous
#include <cuda_runtime.h>
#include <cuda_fp16.h>
#include <cstdint>
#include <math.h>

#define NROW    16384
#define KNBR    16
#define IN_DIM  256
#define HID_DIM 512
#define LN_EPS  1e-5f

// ---------------------------------------------------------------------------
// Low-level helpers (baseline sm_80+ instructions: valid on compute_103)
// ---------------------------------------------------------------------------
__device__ __forceinline__ uint32_t smem_u32(const void* p) {
    uint32_t a;
    asm("{ .reg .u64 t; cvta.to.shared.u64 t, %1; cvt.u32.u64 %0, t; }"
        : "=r"(a) : "l"(p));
    return a;
}
__device__ __forceinline__ void cpasync16(uint32_t dst, const void* src) {
    asm volatile("cp.async.cg.shared.global [%0], [%1], 16;" :: "r"(dst), "l"(src));
}
#define CP_COMMIT() asm volatile("cp.async.commit_group;" ::: "memory")
#define CP_WAIT(n)  asm volatile("cp.async.wait_group %0;" :: "n"(n) : "memory")

__device__ __forceinline__ void ldsm4(uint32_t* r, uint32_t addr) {
    asm volatile("ldmatrix.sync.aligned.m8n8.x4.shared.b16 {%0,%1,%2,%3}, [%4];"
        : "=r"(r[0]), "=r"(r[1]), "=r"(r[2]), "=r"(r[3]) : "r"(addr));
}
__device__ __forceinline__ void mma16816h(float* d, const uint32_t* a, const uint32_t* b) {
    asm volatile("mma.sync.aligned.m16n8k16.row.col.f32.f16.f16.f32 "
        "{%0,%1,%2,%3}, {%4,%5,%6,%7}, {%8,%9}, {%0,%1,%2,%3};"
        : "+f"(d[0]), "+f"(d[1]), "+f"(d[2]), "+f"(d[3])
        : "r"(a[0]), "r"(a[1]), "r"(a[2]), "r"(a[3]), "r"(b[0]), "r"(b[1]));
}
__device__ __forceinline__ int swz(int off) { return off ^ ((off >> 3) & 0x70); }

// Pack two floats into fp16x2 hi word; emit fp16x2 lo word (split residual).
__device__ __forceinline__ uint32_t pack_split_h(float a, float b, uint32_t& lo) {
    __half ha = __float2half_rn(a), hb = __float2half_rn(b);
    float la = a - __half2float(ha);
    float lb = b - __half2float(hb);
    lo = ((uint32_t)__half_as_ushort(__float2half_rn(lb)) << 16) |
         (uint32_t)__half_as_ushort(__float2half_rn(la));
    return ((uint32_t)__half_as_ushort(hb) << 16) |
           (uint32_t)__half_as_ushort(ha);
}

// ---------------------------------------------------------------------------
// Scratch (device globals; no allocation allowed)
// ---------------------------------------------------------------------------
__device__ __half g_data_h[NROW * IN_DIM],  g_data_l[NROW * IN_DIM];
__device__ __half g_h1_h  [NROW * HID_DIM], g_h1_l  [NROW * HID_DIM];
__device__ __half g_h2_h  [NROW * HID_DIM], g_h2_l  [NROW * HID_DIM];
__device__ __half g_loc_h [NROW * HID_DIM], g_loc_l [NROW * HID_DIM];
__device__ __half g_at_h  [NROW * HID_DIM], g_at_l  [NROW * HID_DIM];
__device__ float g_h3   [NROW * HID_DIM];
__device__ float g_pd   [NROW * HID_DIM];
__device__ float g_q    [NROW * HID_DIM];
__device__ float g_k    [NROW * HID_DIM];
__device__ float g_v    [NROW * HID_DIM];
__device__ float g_inter[NROW * HID_DIM];
__device__ float g_pi   [NROW * HID_DIM];
// transposed fp16 weights: [N=512][K]
__device__ __half g_w0t[512 * 256];
__device__ __half g_w1t[512 * 512];
__device__ __half g_w2t[512 * 512];
__device__ __half g_pdt[512 * 256];
__device__ __half g_pit[512 * 256];
__device__ __half g_qt [512 * 512];
__device__ __half g_kt [512 * 512];
__device__ __half g_vt [512 * 512];
__device__ __half g_ot [512 * 512];

// ---------------------------------------------------------------------------
// Batched weight transpose + fp16 round (all 9 weights in one launch).
// Th[n][k] = fp16(W[k][n]).
// ---------------------------------------------------------------------------
struct WJob { const float* W; __half* Th; int K; };
struct WJobs { WJob j[9]; };

__global__ void wsplit_all(WJobs jobs) {
    __shared__ float tile[32][33];
    const WJob jb = jobs.j[blockIdx.z];
    const int n0 = blockIdx.x * 32, k0 = blockIdx.y * 32;
    if (k0 >= jb.K) return;
    for (int i = threadIdx.y; i < 32; i += 8)
        tile[i][threadIdx.x] = jb.W[(size_t)(k0 + i) * 512 + n0 + threadIdx.x];
    __syncthreads();
    for (int i = threadIdx.y; i < 32; i += 8)
        jb.Th[(size_t)(n0 + i) * jb.K + k0 + threadIdx.x] =
            __float2half_rn(tile[threadIdx.x][i]);
}

// fp32 -> fp16 hi/lo split (vectorized, 8 elems/thread)
__global__ void split_f32(const float* __restrict__ x, __half* __restrict__ h,
                          __half* __restrict__ l, int n) {
    int i = (blockIdx.x * 256 + threadIdx.x) * 8;
    if (i >= n) return;
    float4 a = *(const float4*)(x + i);
    float4 b = *(const float4*)(x + i + 4);
    float xs[8] = {a.x, a.y, a.z, a.w, b.x, b.y, b.z, b.w};
    uint32_t ph[4], pl[4];
#pragma unroll
    for (int j = 0; j < 4; j++) ph[j] = pack_split_h(xs[2 * j], xs[2 * j + 1], pl[j]);
    *(uint4*)(h + i) = make_uint4(ph[0], ph[1], ph[2], ph[3]);
    *(uint4*)(l + i) = make_uint4(pl[0], pl[1], pl[2], pl[3]);
}

// ---------------------------------------------------------------------------
// HMMA GEMM: C[M,512] = act(A[M,K] @ W[K,512] + bias)
// A as fp16 hi/lo pair [M,K] (exact split); W rounded fp16, [512][K].
// 2 MMA passes per k-chunk: Ahi*B + Alo*B (fp32 accum).
// BM=BN=128, BK=64, 4-stage cp.async pipeline, 512 threads (16 warps 4x4),
// warp tile 32x32. Stage = Ahi|Alo|B tiles of 16 KB = 48 KB.
// ---------------------------------------------------------------------------
#define STAGE_BYTES 49152
#define GEMM_SMEM   (4 * STAGE_BYTES)

template <int ACT, int WF32, int WPAIR>
__global__ void __launch_bounds__(512, 1)
gemm_hmma(const __half* __restrict__ Ah, const __half* __restrict__ Al,
          const __half* __restrict__ Bw,
          const float* __restrict__ bias, float* __restrict__ Cf,
          __half* __restrict__ Ch, __half* __restrict__ Cl, int Ktot) {
    extern __shared__ __align__(1024) char smem[];
    const uint32_t sb = smem_u32(smem);
    const int tid = threadIdx.x, wid = tid >> 5, lane = tid & 31;
    const int warp_m = wid & 3, warp_n = wid >> 2;   // 4 x 4
    const int bm = blockIdx.y * 128, bn = blockIdx.x * 128;

    const __half* a0 = Ah + (size_t)bm * Ktot;
    const __half* a1 = Al + (size_t)bm * Ktot;
    const __half* b0 = Bw + (size_t)bn * Ktot;

    float acc[2][4][4];
#pragma unroll
    for (int a = 0; a < 2; a++)
#pragma unroll
        for (int b = 0; b < 4; b++)
#pragma unroll
            for (int c = 0; c < 4; c++) acc[a][b][c] = 0.f;

    const int a_row = warp_m * 32 + (lane & 15);                          // + mt*16
    const int a_kb  = ((lane >> 4) & 1) * 16;
    const int b_row = warp_n * 32 + ((lane >> 4) & 1) * 8 + (lane & 7);   // + nt2*16
    const int b_kb  = ((lane >> 3) & 1) * 16;

    const int S = Ktot >> 6;   // S >= 4 for all our GEMMs

    auto load_stage = [&](int buf, int k0) {
        const uint32_t st = sb + buf * STAGE_BYTES;
#pragma unroll
        for (int i = 0; i < 2; i++) {
            const int c   = tid + (i << 9);        // 0..1023
            const int row = c >> 3, kc = c & 7;
            const size_t go = (size_t)row * Ktot + k0 + kc * 8;
            const int so = swz(row * 128 + kc * 16);
            cpasync16(st + so,         a0 + go);
            cpasync16(st + 16384 + so, a1 + go);
            cpasync16(st + 32768 + so, b0 + go);
        }
    };

    load_stage(0, 0);   CP_COMMIT();
    load_stage(1, 64);  CP_COMMIT();
    load_stage(2, 128); CP_COMMIT();

    for (int s = 0; s < S; s++) {
        CP_WAIT(2);            // group for stage s complete
        __syncthreads();
        if (s + 3 < S) load_stage((s + 3) & 3, (s + 3) << 6);
        CP_COMMIT();           // commit (possibly empty) keeps group count invariant

        const uint32_t tb = sb + (s & 3) * STAGE_BYTES;
#pragma unroll
        for (int kk = 0; kk < 4; kk++) {
            uint32_t ah[8], al[8], bh[8];
#pragma unroll
            for (int mt = 0; mt < 2; mt++) {
                const int off = swz((a_row + mt * 16) * 128 + kk * 32 + a_kb);
                ldsm4(ah + 4 * mt, tb + off);
                ldsm4(al + 4 * mt, tb + 16384 + off);
            }
#pragma unroll
            for (int nt2 = 0; nt2 < 2; nt2++) {
                const int off = swz((b_row + nt2 * 16) * 128 + kk * 32 + b_kb);
                ldsm4(bh + 4 * nt2, tb + 32768 + off);
            }
#pragma unroll
            for (int mt = 0; mt < 2; mt++)
#pragma unroll
                for (int nt = 0; nt < 4; nt++) {
                    mma16816h(acc[mt][nt], ah + 4 * mt, bh + nt * 2);
                    mma16816h(acc[mt][nt], al + 4 * mt, bh + nt * 2);
                }
        }
        __syncthreads();
    }

    // ---- epilogue: bias + act + store (fp32 and/or fp16 hi/lo pair) ----
    const int col_base = bn + warp_n * 32 + (lane & 3) * 2;
    const int row_base = bm + warp_m * 32 + (lane >> 2);
#pragma unroll
    for (int nt = 0; nt < 4; nt++) {
        const int col = col_base + nt * 8;
        const float2 bv = *(const float2*)&bias[col];
#pragma unroll
        for (int mt = 0; mt < 2; mt++) {
#pragma unroll
            for (int half_ = 0; half_ < 2; half_++) {
                const int row = row_base + mt * 16 + half_ * 8;
                float v0 = acc[mt][nt][half_ * 2 + 0] + bv.x;
                float v1 = acc[mt][nt][half_ * 2 + 1] + bv.y;
                if (ACT) {
                    v0 = v0 > 0.f ? v0 : expm1f(v0);
                    v1 = v1 > 0.f ? v1 : expm1f(v1);
                }
                if (WF32)
                    *(float2*)(Cf + (size_t)row * 512 + col) = make_float2(v0, v1);
                if (WPAIR) {
                    uint32_t lo, hi = pack_split_h(v0, v1, lo);
                    *(uint32_t*)(Ch + (size_t)row * 512 + col) = hi;
                    *(uint32_t*)(Cl + (size_t)row * 512 + col) = lo;
                }
            }
        }
    }
}

// ---------------------------------------------------------------------------
// Fused residual + LayerNorm (+ optional ELU). OUT: fp32 or fp16 hi/lo pair.
// ---------------------------------------------------------------------------
template <int ACT, int PAIR>
__global__ void __launch_bounds__(256)
ln_res(const float* __restrict__ a, const float* __restrict__ rr, float rscale,
       const float* __restrict__ g, const float* __restrict__ b,
       float* __restrict__ of, __half* __restrict__ oh, __half* __restrict__ ol) {
    __shared__ float red[8];
    const int row = blockIdx.x, t = threadIdx.x;
    const float* ap = a  + (size_t)row * 512;
    const float* rp = rr + (size_t)row * 512;

    float x0 = ap[t]       + rscale * rp[t];
    float x1 = ap[t + 256] + rscale * rp[t + 256];

    float s = x0 + x1;
#pragma unroll
    for (int o = 16; o > 0; o >>= 1) s += __shfl_xor_sync(0xffffffffu, s, o);
    if ((t & 31) == 0) red[t >> 5] = s;
    __syncthreads();
    float mean = 0.f;
#pragma unroll
    for (int w = 0; w < 8; w++) mean += red[w];
    mean *= (1.0f / 512.0f);
    __syncthreads();

    float d0 = x0 - mean, d1 = x1 - mean;
    float vs = d0 * d0 + d1 * d1;
#pragma unroll
    for (int o = 16; o > 0; o >>= 1) vs += __shfl_xor_sync(0xffffffffu, vs, o);
    if ((t & 31) == 0) red[t >> 5] = vs;
    __syncthreads();
    float var = 0.f;
#pragma unroll
    for (int w = 0; w < 8; w++) var += red[w];
    var *= (1.0f / 512.0f);

    const float inv = rsqrtf(var + LN_EPS);
    float y0 = d0 * inv * g[t]       + b[t];
    float y1 = d1 * inv * g[t + 256] + b[t + 256];
    if (ACT) {
        y0 = y0 > 0.f ? y0 : expm1f(y0);
        y1 = y1 > 0.f ? y1 : expm1f(y1);
    }
    if (PAIR) {
        __half h0 = __float2half_rn(y0), h1 = __float2half_rn(y1);
        oh[(size_t)row * 512 + t]       = h0;
        oh[(size_t)row * 512 + t + 256] = h1;
        ol[(size_t)row * 512 + t]       = __float2half_rn(y0 - __half2float(h0));
        ol[(size_t)row * 512 + t + 256] = __float2half_rn(y1 - __half2float(h1));
    } else {
        of[(size_t)row * 512 + t]       = y0;
        of[(size_t)row * 512 + t + 256] = y1;
    }
}

// ---------------------------------------------------------------------------
// Neighbor attention (one warp per node). Emits fp16 hi/lo pair for o-GEMM.
// ---------------------------------------------------------------------------
__global__ void __launch_bounds__(256)
nbr_attn(const float* __restrict__ q, const float* __restrict__ kc,
         const float* __restrict__ vc, const int* __restrict__ nbrs,
         __half* __restrict__ oh, __half* __restrict__ ol) {
    const int warp = threadIdx.x >> 5;
    const int lane = threadIdx.x & 31;
    const int node = blockIdx.x * 8 + warp;

    const size_t base = (size_t)node * 512 + lane * 16;
    float qr[16];
#pragma unroll
    for (int i = 0; i < 16; i += 4) {
        float4 t = *reinterpret_cast<const float4*>(q + base + i);
        qr[i] = t.x; qr[i + 1] = t.y; qr[i + 2] = t.z; qr[i + 3] = t.w;
    }

    float m = -1e30f, s = 0.f;
    float acc[16];
#pragma unroll
    for (int i = 0; i < 16; i++) acc[i] = 0.f;

#pragma unroll
    for (int j = 0; j < KNBR; j++) {
        const int nb = __ldg(&nbrs[node * KNBR + j]);
        const float* kp = kc + (size_t)nb * 512 + lane * 16;
        const float* vp = vc + (size_t)nb * 512 + lane * 16;

        float dot = 0.f;
        float vr[16];
#pragma unroll
        for (int i = 0; i < 16; i += 4) {
            float4 kv = *reinterpret_cast<const float4*>(kp + i);
            float4 vv = *reinterpret_cast<const float4*>(vp + i);
            dot = fmaf(kv.x, qr[i],     dot);
            dot = fmaf(kv.y, qr[i + 1], dot);
            dot = fmaf(kv.z, qr[i + 2], dot);
            dot = fmaf(kv.w, qr[i + 3], dot);
            vr[i] = vv.x; vr[i + 1] = vv.y; vr[i + 2] = vv.z; vr[i + 3] = vv.w;
        }
        dot += __shfl_xor_sync(0xffffffffu, dot, 1);
        dot += __shfl_xor_sync(0xffffffffu, dot, 2);
        const float score = dot * 0.125f;

        const float mn   = fmaxf(m, score);
        const float corr = __expf(m - mn);
        const float p    = __expf(score - mn);
        s = s * corr + p;
#pragma unroll
        for (int i = 0; i < 16; i++) acc[i] = acc[i] * corr + p * vr[i];
        m = mn;
    }

    const float inv = 1.f / s;
    uint32_t ph[8], pl[8];
#pragma unroll
    for (int j = 0; j < 8; j++)
        ph[j] = pack_split_h(acc[2 * j] * inv, acc[2 * j + 1] * inv, pl[j]);
    *(uint4*)(oh + base)     = make_uint4(ph[0], ph[1], ph[2], ph[3]);
    *(uint4*)(oh + base + 8) = make_uint4(ph[4], ph[5], ph[6], ph[7]);
    *(uint4*)(ol + base)     = make_uint4(pl[0], pl[1], pl[2], pl[3]);
    *(uint4*)(ol + base + 8) = make_uint4(pl[4], pl[5], pl[6], pl[7]);
}

// ---------------------------------------------------------------------------
// Launch
// ---------------------------------------------------------------------------
extern "C" void kernel_launch(void* const* d_in, const int* in_sizes, int n_in,
                              void* d_out, int out_size) {
    (void)in_sizes; (void)n_in; (void)out_size;
    const float* data   = (const float*)d_in[0];
    const int*   nbrs   = (const int*)  d_in[1];
    const float* mlp_w0 = (const float*)d_in[2];
    const float* mlp_b0 = (const float*)d_in[3];
    const float* mlp_w1 = (const float*)d_in[4];
    const float* mlp_b1 = (const float*)d_in[5];
    const float* mlp_w2 = (const float*)d_in[6];
    const float* mlp_b2 = (const float*)d_in[7];
    const float* pd_w   = (const float*)d_in[8];
    const float* pd_b   = (const float*)d_in[9];
    const float* pi_w   = (const float*)d_in[10];
    const float* pi_b   = (const float*)d_in[11];
    const float* q_w    = (const float*)d_in[12];
    const float* q_b    = (const float*)d_in[13];
    const float* k_w    = (const float*)d_in[14];
    const float* k_b    = (const float*)d_in[15];
    const float* v_w    = (const float*)d_in[16];
    const float* v_b    = (const float*)d_in[17];
    const float* o_w    = (const float*)d_in[18];
    const float* o_b    = (const float*)d_in[19];
    const float* ln1_g  = (const float*)d_in[20];
    const float* ln1_b  = (const float*)d_in[21];
    const float* ln2_g  = (const float*)d_in[22];
    const float* ln2_b  = (const float*)d_in[23];
    float* out = (float*)d_out;

    __half *data_h, *data_l, *h1_h, *h1_l, *h2_h, *h2_l, *loc_h, *loc_l, *at_h, *at_l;
    float *h3, *pd, *qb, *kb, *vb, *inter, *pi;
    __half *w0t, *w1t, *w2t, *pdt, *pit, *qt, *kt, *vt, *ot;
    cudaGetSymbolAddress((void**)&data_h, g_data_h); cudaGetSymbolAddress((void**)&data_l, g_data_l);
    cudaGetSymbolAddress((void**)&h1_h, g_h1_h);     cudaGetSymbolAddress((void**)&h1_l, g_h1_l);
    cudaGetSymbolAddress((void**)&h2_h, g_h2_h);     cudaGetSymbolAddress((void**)&h2_l, g_h2_l);
    cudaGetSymbolAddress((void**)&loc_h, g_loc_h);   cudaGetSymbolAddress((void**)&loc_l, g_loc_l);
    cudaGetSymbolAddress((void**)&at_h, g_at_h);     cudaGetSymbolAddress((void**)&at_l, g_at_l);
    cudaGetSymbolAddress((void**)&h3, g_h3);         cudaGetSymbolAddress((void**)&pd, g_pd);
    cudaGetSymbolAddress((void**)&qb, g_q);          cudaGetSymbolAddress((void**)&kb, g_k);
    cudaGetSymbolAddress((void**)&vb, g_v);          cudaGetSymbolAddress((void**)&inter, g_inter);
    cudaGetSymbolAddress((void**)&pi, g_pi);
    cudaGetSymbolAddress((void**)&w0t, g_w0t); cudaGetSymbolAddress((void**)&w1t, g_w1t);
    cudaGetSymbolAddress((void**)&w2t, g_w2t); cudaGetSymbolAddress((void**)&pdt, g_pdt);
    cudaGetSymbolAddress((void**)&pit, g_pit); cudaGetSymbolAddress((void**)&qt,  g_qt);
    cudaGetSymbolAddress((void**)&kt,  g_kt);  cudaGetSymbolAddress((void**)&vt,  g_vt);
    cudaGetSymbolAddress((void**)&ot,  g_ot);

    cudaFuncSetAttribute(gemm_hmma<1, 0, 1>, cudaFuncAttributeMaxDynamicSharedMemorySize, GEMM_SMEM);
    cudaFuncSetAttribute(gemm_hmma<0, 1, 0>, cudaFuncAttributeMaxDynamicSharedMemorySize, GEMM_SMEM);

    WJobs jobs;
    jobs.j[0] = {mlp_w0, w0t, 256};
    jobs.j[1] = {mlp_w1, w1t, 512};
    jobs.j[2] = {mlp_w2, w2t, 512};
    jobs.j[3] = {pd_w,   pdt, 256};
    jobs.j[4] = {pi_w,   pit, 256};
    jobs.j[5] = {q_w,    qt,  512};
    jobs.j[6] = {k_w,    kt,  512};
    jobs.j[7] = {v_w,    vt,  512};
    jobs.j[8] = {o_w,    ot,  512};

    const dim3 gg(4, 128);

    // 0: all weight transposes (fp16 round)
    wsplit_all<<<dim3(16, 16, 9), dim3(32, 8)>>>(jobs);
    // 1: data split (fp16 hi/lo)
    split_f32<<<(NROW * IN_DIM) / (256 * 8), 256>>>(data, data_h, data_l, NROW * IN_DIM);
    // 2..5: GEMMs (profiler sample lands on one of these)
    gemm_hmma<1, 0, 1><<<gg, 512, GEMM_SMEM>>>(data_h, data_l, w0t, mlp_b0, nullptr, h1_h, h1_l, 256);
    gemm_hmma<1, 0, 1><<<gg, 512, GEMM_SMEM>>>(h1_h, h1_l,   w1t, mlp_b1, nullptr, h2_h, h2_l, 512);
    gemm_hmma<0, 1, 0><<<gg, 512, GEMM_SMEM>>>(h2_h, h2_l,   w2t, mlp_b2, h3, nullptr, nullptr, 512);
    gemm_hmma<0, 1, 0><<<gg, 512, GEMM_SMEM>>>(data_h, data_l, pdt, pd_b, pd, nullptr, nullptr, 256);
    // 6: local = elu(LN(h3 + 2*pd)) -> fp16 pair
    ln_res<1, 1><<<NROW, 256>>>(h3, pd, 2.0f, ln1_g, ln1_b, nullptr, loc_h, loc_l);
    // 7-9: Q, K, V projections (fp32 outputs for attention)
    gemm_hmma<0, 1, 0><<<gg, 512, GEMM_SMEM>>>(loc_h, loc_l, qt, q_b, qb, nullptr, nullptr, 512);
    gemm_hmma<0, 1, 0><<<gg, 512, GEMM_SMEM>>>(loc_h, loc_l, kt, k_b, kb, nullptr, nullptr, 512);
    gemm_hmma<0, 1, 0><<<gg, 512, GEMM_SMEM>>>(loc_h, loc_l, vt, v_b, vb, nullptr, nullptr, 512);
    // 10: neighbor attention -> fp16 pair
    nbr_attn<<<NROW / 8, 256>>>(qb, kb, vb, nbrs, at_h, at_l);
    // 11-12: output projection + project_in
    gemm_hmma<0, 1, 0><<<gg, 512, GEMM_SMEM>>>(at_h, at_l, ot, o_b, inter, nullptr, nullptr, 512);
    gemm_hmma<0, 1, 0><<<gg, 512, GEMM_SMEM>>>(data_h, data_l, pit, pi_b, pi, nullptr, nullptr, 256);
    // 13: out = LN(inter + pi)
    ln_res<0, 0><<<NROW, 256>>>(inter, pi, 1.0f, ln2_g, ln2_b, out, nullptr, nullptr);
}

// round 9
// speedup vs baseline: 1.5992x; 1.3012x over previous
#include <cuda_runtime.h>
#include <cuda_fp16.h>
#include <cstdint>
#include <math.h>

#define NROW    16384
#define KNBR    16
#define IN_DIM  256
#define HID_DIM 512
#define LN_EPS  1e-5f

// ---------------------------------------------------------------------------
// Low-level helpers (baseline sm_80+ instructions: valid on compute_103)
// ---------------------------------------------------------------------------
__device__ __forceinline__ uint32_t smem_u32(const void* p) {
    uint32_t a;
    asm("{ .reg .u64 t; cvta.to.shared.u64 t, %1; cvt.u32.u64 %0, t; }"
        : "=r"(a) : "l"(p));
    return a;
}
__device__ __forceinline__ void cpasync16(uint32_t dst, const void* src) {
    asm volatile("cp.async.cg.shared.global [%0], [%1], 16;" :: "r"(dst), "l"(src));
}
#define CP_COMMIT() asm volatile("cp.async.commit_group;" ::: "memory")
#define CP_WAIT(n)  asm volatile("cp.async.wait_group %0;" :: "n"(n) : "memory")

__device__ __forceinline__ void ldsm4(uint32_t* r, uint32_t addr) {
    asm volatile("ldmatrix.sync.aligned.m8n8.x4.shared.b16 {%0,%1,%2,%3}, [%4];"
        : "=r"(r[0]), "=r"(r[1]), "=r"(r[2]), "=r"(r[3]) : "r"(addr));
}
__device__ __forceinline__ void mma16816h(float* d, const uint32_t* a, const uint32_t* b) {
    asm volatile("mma.sync.aligned.m16n8k16.row.col.f32.f16.f16.f32 "
        "{%0,%1,%2,%3}, {%4,%5,%6,%7}, {%8,%9}, {%0,%1,%2,%3};"
        : "+f"(d[0]), "+f"(d[1]), "+f"(d[2]), "+f"(d[3])
        : "r"(a[0]), "r"(a[1]), "r"(a[2]), "r"(a[3]), "r"(b[0]), "r"(b[1]));
}
__device__ __forceinline__ int swz(int off) { return off ^ ((off >> 3) & 0x70); }

__device__ __forceinline__ uint32_t pack_h2(float a, float b) {
    return ((uint32_t)__half_as_ushort(__float2half_rn(b)) << 16) |
           (uint32_t)__half_as_ushort(__float2half_rn(a));
}

// ---------------------------------------------------------------------------
// Scratch (device globals; no allocation allowed)
// ---------------------------------------------------------------------------
__device__ __half g_data_h[NROW * IN_DIM];
__device__ __half g_h1_h  [NROW * HID_DIM];
__device__ __half g_h2_h  [NROW * HID_DIM];
__device__ __half g_loc_h [NROW * HID_DIM];
__device__ __half g_at_h  [NROW * HID_DIM];
__device__ float g_h3   [NROW * HID_DIM];
__device__ float g_pd   [NROW * HID_DIM];
__device__ float g_q    [NROW * HID_DIM];
__device__ float g_k    [NROW * HID_DIM];
__device__ float g_v    [NROW * HID_DIM];
__device__ float g_inter[NROW * HID_DIM];
__device__ float g_pi   [NROW * HID_DIM];
// transposed fp16 weights: [N=512][K]
__device__ __half g_w0t[512 * 256];
__device__ __half g_w1t[512 * 512];
__device__ __half g_w2t[512 * 512];
__device__ __half g_pdt[512 * 256];
__device__ __half g_pit[512 * 256];
__device__ __half g_qt [512 * 512];
__device__ __half g_kt [512 * 512];
__device__ __half g_vt [512 * 512];
__device__ __half g_ot [512 * 512];

// ---------------------------------------------------------------------------
// Batched weight transpose + fp16 round (all 9 weights in one launch).
// ---------------------------------------------------------------------------
struct WJob { const float* W; __half* Th; int K; };
struct WJobs { WJob j[9]; };

__global__ void wsplit_all(WJobs jobs) {
    __shared__ float tile[32][33];
    const WJob jb = jobs.j[blockIdx.z];
    const int n0 = blockIdx.x * 32, k0 = blockIdx.y * 32;
    if (k0 >= jb.K) return;
    for (int i = threadIdx.y; i < 32; i += 8)
        tile[i][threadIdx.x] = jb.W[(size_t)(k0 + i) * 512 + n0 + threadIdx.x];
    __syncthreads();
    for (int i = threadIdx.y; i < 32; i += 8)
        jb.Th[(size_t)(n0 + i) * jb.K + k0 + threadIdx.x] =
            __float2half_rn(tile[threadIdx.x][i]);
}

// fp32 -> fp16 (vectorized, 8 elems/thread)
__global__ void split_f32(const float* __restrict__ x, __half* __restrict__ h, int n) {
    int i = (blockIdx.x * 256 + threadIdx.x) * 8;
    if (i >= n) return;
    float4 a = *(const float4*)(x + i);
    float4 b = *(const float4*)(x + i + 4);
    *(uint4*)(h + i) = make_uint4(pack_h2(a.x, a.y), pack_h2(a.z, a.w),
                                  pack_h2(b.x, b.y), pack_h2(b.z, b.w));
}

// ---------------------------------------------------------------------------
// HMMA GEMM: C[M,512] = act(A[M,K] @ W[K,512] + bias)
// A rounded fp16 [M,K]; W rounded fp16 [512][K] (col-major B). 1 MMA pass.
// BM=BN=128, BK=64, 4-stage cp.async pipeline, 512 threads (16 warps 4x4),
// warp tile 32x32. Stage = A|B tiles of 16 KB = 32 KB.
// ---------------------------------------------------------------------------
#define STAGE_BYTES 32768
#define GEMM_SMEM   (4 * STAGE_BYTES)

template <int ACT, int WF32, int WH16>
__global__ void __launch_bounds__(512, 1)
gemm_hmma(const __half* __restrict__ Ah, const __half* __restrict__ Bw,
          const float* __restrict__ bias, float* __restrict__ Cf,
          __half* __restrict__ Ch, int Ktot) {
    extern __shared__ __align__(1024) char smem[];
    const uint32_t sb = smem_u32(smem);
    const int tid = threadIdx.x, wid = tid >> 5, lane = tid & 31;
    const int warp_m = wid & 3, warp_n = wid >> 2;   // 4 x 4
    const int bm = blockIdx.y * 128, bn = blockIdx.x * 128;

    const __half* a0 = Ah + (size_t)bm * Ktot;
    const __half* b0 = Bw + (size_t)bn * Ktot;

    float acc[2][4][4];
#pragma unroll
    for (int a = 0; a < 2; a++)
#pragma unroll
        for (int b = 0; b < 4; b++)
#pragma unroll
            for (int c = 0; c < 4; c++) acc[a][b][c] = 0.f;

    const int a_row = warp_m * 32 + (lane & 15);                          // + mt*16
    const int a_kb  = ((lane >> 4) & 1) * 16;
    const int b_row = warp_n * 32 + ((lane >> 4) & 1) * 8 + (lane & 7);   // + nt2*16
    const int b_kb  = ((lane >> 3) & 1) * 16;

    const int S = Ktot >> 6;   // >= 4 for all our GEMMs

    auto load_stage = [&](int buf, int k0) {
        const uint32_t st = sb + buf * STAGE_BYTES;
#pragma unroll
        for (int i = 0; i < 2; i++) {
            const int c   = tid + (i << 9);        // 0..1023
            const int row = c >> 3, kc = c & 7;
            const size_t go = (size_t)row * Ktot + k0 + kc * 8;
            const int so = swz(row * 128 + kc * 16);
            cpasync16(st + so,         a0 + go);
            cpasync16(st + 16384 + so, b0 + go);
        }
    };

    load_stage(0, 0);   CP_COMMIT();
    load_stage(1, 64);  CP_COMMIT();
    load_stage(2, 128); CP_COMMIT();

    for (int s = 0; s < S; s++) {
        CP_WAIT(2);
        __syncthreads();
        if (s + 3 < S) load_stage((s + 3) & 3, (s + 3) << 6);
        CP_COMMIT();

        const uint32_t tb = sb + (s & 3) * STAGE_BYTES;
#pragma unroll
        for (int kk = 0; kk < 4; kk++) {
            uint32_t ah[8], bh[8];
#pragma unroll
            for (int mt = 0; mt < 2; mt++) {
                const int off = swz((a_row + mt * 16) * 128 + kk * 32 + a_kb);
                ldsm4(ah + 4 * mt, tb + off);
            }
#pragma unroll
            for (int nt2 = 0; nt2 < 2; nt2++) {
                const int off = swz((b_row + nt2 * 16) * 128 + kk * 32 + b_kb);
                ldsm4(bh + 4 * nt2, tb + 16384 + off);
            }
#pragma unroll
            for (int mt = 0; mt < 2; mt++)
#pragma unroll
                for (int nt = 0; nt < 4; nt++)
                    mma16816h(acc[mt][nt], ah + 4 * mt, bh + nt * 2);
        }
        __syncthreads();
    }

    // ---- epilogue: bias + act + store (fp32 and/or fp16) ----
    const int col_base = bn + warp_n * 32 + (lane & 3) * 2;
    const int row_base = bm + warp_m * 32 + (lane >> 2);
#pragma unroll
    for (int nt = 0; nt < 4; nt++) {
        const int col = col_base + nt * 8;
        const float2 bv = *(const float2*)&bias[col];
#pragma unroll
        for (int mt = 0; mt < 2; mt++) {
#pragma unroll
            for (int half_ = 0; half_ < 2; half_++) {
                const int row = row_base + mt * 16 + half_ * 8;
                float v0 = acc[mt][nt][half_ * 2 + 0] + bv.x;
                float v1 = acc[mt][nt][half_ * 2 + 1] + bv.y;
                if (ACT) {
                    v0 = v0 > 0.f ? v0 : expm1f(v0);
                    v1 = v1 > 0.f ? v1 : expm1f(v1);
                }
                if (WF32)
                    *(float2*)(Cf + (size_t)row * 512 + col) = make_float2(v0, v1);
                if (WH16)
                    *(uint32_t*)(Ch + (size_t)row * 512 + col) = pack_h2(v0, v1);
            }
        }
    }
}

// ---------------------------------------------------------------------------
// Fused residual + LayerNorm (+ optional ELU). OUT: fp32 or fp16.
// ---------------------------------------------------------------------------
template <int ACT, int H16>
__global__ void __launch_bounds__(256)
ln_res(const float* __restrict__ a, const float* __restrict__ rr, float rscale,
       const float* __restrict__ g, const float* __restrict__ b,
       float* __restrict__ of, __half* __restrict__ oh) {
    __shared__ float red[8];
    const int row = blockIdx.x, t = threadIdx.x;
    const float* ap = a  + (size_t)row * 512;
    const float* rp = rr + (size_t)row * 512;

    float x0 = ap[t]       + rscale * rp[t];
    float x1 = ap[t + 256] + rscale * rp[t + 256];

    float s = x0 + x1;
#pragma unroll
    for (int o = 16; o > 0; o >>= 1) s += __shfl_xor_sync(0xffffffffu, s, o);
    if ((t & 31) == 0) red[t >> 5] = s;
    __syncthreads();
    float mean = 0.f;
#pragma unroll
    for (int w = 0; w < 8; w++) mean += red[w];
    mean *= (1.0f / 512.0f);
    __syncthreads();

    float d0 = x0 - mean, d1 = x1 - mean;
    float vs = d0 * d0 + d1 * d1;
#pragma unroll
    for (int o = 16; o > 0; o >>= 1) vs += __shfl_xor_sync(0xffffffffu, vs, o);
    if ((t & 31) == 0) red[t >> 5] = vs;
    __syncthreads();
    float var = 0.f;
#pragma unroll
    for (int w = 0; w < 8; w++) var += red[w];
    var *= (1.0f / 512.0f);

    const float inv = rsqrtf(var + LN_EPS);
    float y0 = d0 * inv * g[t]       + b[t];
    float y1 = d1 * inv * g[t + 256] + b[t + 256];
    if (ACT) {
        y0 = y0 > 0.f ? y0 : expm1f(y0);
        y1 = y1 > 0.f ? y1 : expm1f(y1);
    }
    if (H16) {
        oh[(size_t)row * 512 + t]       = __float2half_rn(y0);
        oh[(size_t)row * 512 + t + 256] = __float2half_rn(y1);
    } else {
        of[(size_t)row * 512 + t]       = y0;
        of[(size_t)row * 512 + t + 256] = y1;
    }
}

// ---------------------------------------------------------------------------
// Neighbor attention (one warp per node). fp32 in, fp16 out (for o-GEMM).
// ---------------------------------------------------------------------------
__global__ void __launch_bounds__(256)
nbr_attn(const float* __restrict__ q, const float* __restrict__ kc,
         const float* __restrict__ vc, const int* __restrict__ nbrs,
         __half* __restrict__ oh) {
    const int warp = threadIdx.x >> 5;
    const int lane = threadIdx.x & 31;
    const int node = blockIdx.x * 8 + warp;

    const size_t base = (size_t)node * 512 + lane * 16;
    float qr[16];
#pragma unroll
    for (int i = 0; i < 16; i += 4) {
        float4 t = *reinterpret_cast<const float4*>(q + base + i);
        qr[i] = t.x; qr[i + 1] = t.y; qr[i + 2] = t.z; qr[i + 3] = t.w;
    }

    float m = -1e30f, s = 0.f;
    float acc[16];
#pragma unroll
    for (int i = 0; i < 16; i++) acc[i] = 0.f;

#pragma unroll
    for (int j = 0; j < KNBR; j++) {
        const int nb = __ldg(&nbrs[node * KNBR + j]);
        const float* kp = kc + (size_t)nb * 512 + lane * 16;
        const float* vp = vc + (size_t)nb * 512 + lane * 16;

        float dot = 0.f;
        float vr[16];
#pragma unroll
        for (int i = 0; i < 16; i += 4) {
            float4 kv = *reinterpret_cast<const float4*>(kp + i);
            float4 vv = *reinterpret_cast<const float4*>(vp + i);
            dot = fmaf(kv.x, qr[i],     dot);
            dot = fmaf(kv.y, qr[i + 1], dot);
            dot = fmaf(kv.z, qr[i + 2], dot);
            dot = fmaf(kv.w, qr[i + 3], dot);
            vr[i] = vv.x; vr[i + 1] = vv.y; vr[i + 2] = vv.z; vr[i + 3] = vv.w;
        }
        dot += __shfl_xor_sync(0xffffffffu, dot, 1);
        dot += __shfl_xor_sync(0xffffffffu, dot, 2);
        const float score = dot * 0.125f;

        const float mn   = fmaxf(m, score);
        const float corr = __expf(m - mn);
        const float p    = __expf(score - mn);
        s = s * corr + p;
#pragma unroll
        for (int i = 0; i < 16; i++) acc[i] = acc[i] * corr + p * vr[i];
        m = mn;
    }

    const float inv = 1.f / s;
    uint32_t ph[8];
#pragma unroll
    for (int j = 0; j < 8; j++)
        ph[j] = pack_h2(acc[2 * j] * inv, acc[2 * j + 1] * inv);
    *(uint4*)(oh + base)     = make_uint4(ph[0], ph[1], ph[2], ph[3]);
    *(uint4*)(oh + base + 8) = make_uint4(ph[4], ph[5], ph[6], ph[7]);
}

// ---------------------------------------------------------------------------
// Launch
// ---------------------------------------------------------------------------
extern "C" void kernel_launch(void* const* d_in, const int* in_sizes, int n_in,
                              void* d_out, int out_size) {
    (void)in_sizes; (void)n_in; (void)out_size;
    const float* data   = (const float*)d_in[0];
    const int*   nbrs   = (const int*)  d_in[1];
    const float* mlp_w0 = (const float*)d_in[2];
    const float* mlp_b0 = (const float*)d_in[3];
    const float* mlp_w1 = (const float*)d_in[4];
    const float* mlp_b1 = (const float*)d_in[5];
    const float* mlp_w2 = (const float*)d_in[6];
    const float* mlp_b2 = (const float*)d_in[7];
    const float* pd_w   = (const float*)d_in[8];
    const float* pd_b   = (const float*)d_in[9];
    const float* pi_w   = (const float*)d_in[10];
    const float* pi_b   = (const float*)d_in[11];
    const float* q_w    = (const float*)d_in[12];
    const float* q_b    = (const float*)d_in[13];
    const float* k_w    = (const float*)d_in[14];
    const float* k_b    = (const float*)d_in[15];
    const float* v_w    = (const float*)d_in[16];
    const float* v_b    = (const float*)d_in[17];
    const float* o_w    = (const float*)d_in[18];
    const float* o_b    = (const float*)d_in[19];
    const float* ln1_g  = (const float*)d_in[20];
    const float* ln1_b  = (const float*)d_in[21];
    const float* ln2_g  = (const float*)d_in[22];
    const float* ln2_b  = (const float*)d_in[23];
    float* out = (float*)d_out;

    __half *data_h, *h1_h, *h2_h, *loc_h, *at_h;
    float *h3, *pd, *qb, *kb, *vb, *inter, *pi;
    __half *w0t, *w1t, *w2t, *pdt, *pit, *qt, *kt, *vt, *ot;
    cudaGetSymbolAddress((void**)&data_h, g_data_h);
    cudaGetSymbolAddress((void**)&h1_h, g_h1_h);
    cudaGetSymbolAddress((void**)&h2_h, g_h2_h);
    cudaGetSymbolAddress((void**)&loc_h, g_loc_h);
    cudaGetSymbolAddress((void**)&at_h, g_at_h);
    cudaGetSymbolAddress((void**)&h3, g_h3);   cudaGetSymbolAddress((void**)&pd, g_pd);
    cudaGetSymbolAddress((void**)&qb, g_q);    cudaGetSymbolAddress((void**)&kb, g_k);
    cudaGetSymbolAddress((void**)&vb, g_v);    cudaGetSymbolAddress((void**)&inter, g_inter);
    cudaGetSymbolAddress((void**)&pi, g_pi);
    cudaGetSymbolAddress((void**)&w0t, g_w0t); cudaGetSymbolAddress((void**)&w1t, g_w1t);
    cudaGetSymbolAddress((void**)&w2t, g_w2t); cudaGetSymbolAddress((void**)&pdt, g_pdt);
    cudaGetSymbolAddress((void**)&pit, g_pit); cudaGetSymbolAddress((void**)&qt,  g_qt);
    cudaGetSymbolAddress((void**)&kt,  g_kt);  cudaGetSymbolAddress((void**)&vt,  g_vt);
    cudaGetSymbolAddress((void**)&ot,  g_ot);

    cudaFuncSetAttribute(gemm_hmma<1, 0, 1>, cudaFuncAttributeMaxDynamicSharedMemorySize, GEMM_SMEM);
    cudaFuncSetAttribute(gemm_hmma<0, 1, 0>, cudaFuncAttributeMaxDynamicSharedMemorySize, GEMM_SMEM);

    WJobs jobs;
    jobs.j[0] = {mlp_w0, w0t, 256};
    jobs.j[1] = {mlp_w1, w1t, 512};
    jobs.j[2] = {mlp_w2, w2t, 512};
    jobs.j[3] = {pd_w,   pdt, 256};
    jobs.j[4] = {pi_w,   pit, 256};
    jobs.j[5] = {q_w,    qt,  512};
    jobs.j[6] = {k_w,    kt,  512};
    jobs.j[7] = {v_w,    vt,  512};
    jobs.j[8] = {o_w,    ot,  512};

    const dim3 gg(4, 128);

    // 0: all weight transposes (fp16 round)
    wsplit_all<<<dim3(16, 16, 9), dim3(32, 8)>>>(jobs);
    // 1: data -> fp16
    split_f32<<<(NROW * IN_DIM) / (256 * 8), 256>>>(data, data_h, NROW * IN_DIM);
    // 2..5: GEMMs
    gemm_hmma<1, 0, 1><<<gg, 512, GEMM_SMEM>>>(data_h, w0t, mlp_b0, nullptr, h1_h, 256);
    gemm_hmma<1, 0, 1><<<gg, 512, GEMM_SMEM>>>(h1_h,   w1t, mlp_b1, nullptr, h2_h, 512);
    gemm_hmma<0, 1, 0><<<gg, 512, GEMM_SMEM>>>(h2_h,   w2t, mlp_b2, h3, nullptr, 512);
    gemm_hmma<0, 1, 0><<<gg, 512, GEMM_SMEM>>>(data_h, pdt, pd_b,   pd, nullptr, 256);
    // 6: local = elu(LN(h3 + 2*pd)) -> fp16
    ln_res<1, 1><<<NROW, 256>>>(h3, pd, 2.0f, ln1_g, ln1_b, nullptr, loc_h);
    // 7-9: Q, K, V projections (fp32 outputs for attention)
    gemm_hmma<0, 1, 0><<<gg, 512, GEMM_SMEM>>>(loc_h, qt, q_b, qb, nullptr, 512);
    gemm_hmma<0, 1, 0><<<gg, 512, GEMM_SMEM>>>(loc_h, kt, k_b, kb, nullptr, 512);
    gemm_hmma<0, 1, 0><<<gg, 512, GEMM_SMEM>>>(loc_h, vt, v_b, vb, nullptr, 512);
    // 10: neighbor attention -> fp16
    nbr_attn<<<NROW / 8, 256>>>(qb, kb, vb, nbrs, at_h);
    // 11-12: output projection + project_in
    gemm_hmma<0, 1, 0><<<gg, 512, GEMM_SMEM>>>(at_h,   ot,  o_b,  inter, nullptr, 512);
    gemm_hmma<0, 1, 0><<<gg, 512, GEMM_SMEM>>>(data_h, pit, pi_b, pi,    nullptr, 256);
    // 13: out = LN(inter + pi)
    ln_res<0, 0><<<NROW, 256>>>(inter, pi, 1.0f, ln2_g, ln2_b, out, nullptr);
}

// round 10
// speedup vs baseline: 2.2491x; 1.4064x over previous
#include <cuda_runtime.h>
#include <cuda_fp16.h>
#include <cstdint>
#include <math.h>

#define NROW    16384
#define KNBR    16
#define IN_DIM  256
#define HID_DIM 512
#define LN_EPS  1e-5f

// ---------------------------------------------------------------------------
// Low-level helpers (baseline sm_80+ instructions: valid on compute_103)
// ---------------------------------------------------------------------------
__device__ __forceinline__ uint32_t smem_u32(const void* p) {
    uint32_t a;
    asm("{ .reg .u64 t; cvta.to.shared.u64 t, %1; cvt.u32.u64 %0, t; }"
        : "=r"(a) : "l"(p));
    return a;
}
__device__ __forceinline__ void cpasync16(uint32_t dst, const void* src) {
    asm volatile("cp.async.cg.shared.global [%0], [%1], 16;" :: "r"(dst), "l"(src));
}
#define CP_COMMIT() asm volatile("cp.async.commit_group;" ::: "memory")
#define CP_WAIT(n)  asm volatile("cp.async.wait_group %0;" :: "n"(n) : "memory")

__device__ __forceinline__ void ldsm4(uint32_t* r, uint32_t addr) {
    asm volatile("ldmatrix.sync.aligned.m8n8.x4.shared.b16 {%0,%1,%2,%3}, [%4];"
        : "=r"(r[0]), "=r"(r[1]), "=r"(r[2]), "=r"(r[3]) : "r"(addr));
}
__device__ __forceinline__ void mma16816h(float* d, const uint32_t* a, const uint32_t* b) {
    asm volatile("mma.sync.aligned.m16n8k16.row.col.f32.f16.f16.f32 "
        "{%0,%1,%2,%3}, {%4,%5,%6,%7}, {%8,%9}, {%0,%1,%2,%3};"
        : "+f"(d[0]), "+f"(d[1]), "+f"(d[2]), "+f"(d[3])
        : "r"(a[0]), "r"(a[1]), "r"(a[2]), "r"(a[3]), "r"(b[0]), "r"(b[1]));
}
__device__ __forceinline__ int swz(int off) { return off ^ ((off >> 3) & 0x70); }

__device__ __forceinline__ uint32_t pack_h2(float a, float b) {
    return ((uint32_t)__half_as_ushort(__float2half_rn(b)) << 16) |
           (uint32_t)__half_as_ushort(__float2half_rn(a));
}
__device__ __forceinline__ void h8_to_f(const uint4& u, float* f) {
    const __half2* h = reinterpret_cast<const __half2*>(&u);
#pragma unroll
    for (int j = 0; j < 4; j++) {
        float2 t = __half22float2(h[j]);
        f[2 * j] = t.x; f[2 * j + 1] = t.y;
    }
}

// ---------------------------------------------------------------------------
// Scratch (device globals; no allocation allowed)
// ---------------------------------------------------------------------------
__device__ __half g_data_h[NROW * IN_DIM];
__device__ __half g_h1_h  [NROW * HID_DIM];
__device__ __half g_h2_h  [NROW * HID_DIM];
__device__ __half g_loc_h [NROW * HID_DIM];
__device__ __half g_at_h  [NROW * HID_DIM];
__device__ __half g_qh    [NROW * HID_DIM];
__device__ __half g_kh    [NROW * HID_DIM];
__device__ __half g_vh    [NROW * HID_DIM];
__device__ float g_h3   [NROW * HID_DIM];
__device__ float g_pd   [NROW * HID_DIM];
__device__ float g_inter[NROW * HID_DIM];
__device__ float g_pi   [NROW * HID_DIM];
// transposed fp16 weights: [N=512][K]
__device__ __half g_w0t[512 * 256];
__device__ __half g_w1t[512 * 512];
__device__ __half g_w2t[512 * 512];
__device__ __half g_pdt[512 * 256];
__device__ __half g_pit[512 * 256];
__device__ __half g_qt [512 * 512];
__device__ __half g_kt [512 * 512];
__device__ __half g_vt [512 * 512];
__device__ __half g_ot [512 * 512];

// ---------------------------------------------------------------------------
// Batched weight transpose + fp16 round (all 9 weights in one launch).
// ---------------------------------------------------------------------------
struct WJob { const float* W; __half* Th; int K; };
struct WJobs { WJob j[9]; };

__global__ void wsplit_all(WJobs jobs) {
    __shared__ float tile[32][33];
    const WJob jb = jobs.j[blockIdx.z];
    const int n0 = blockIdx.x * 32, k0 = blockIdx.y * 32;
    if (k0 >= jb.K) return;
    for (int i = threadIdx.y; i < 32; i += 8)
        tile[i][threadIdx.x] = jb.W[(size_t)(k0 + i) * 512 + n0 + threadIdx.x];
    __syncthreads();
    for (int i = threadIdx.y; i < 32; i += 8)
        jb.Th[(size_t)(n0 + i) * jb.K + k0 + threadIdx.x] =
            __float2half_rn(tile[threadIdx.x][i]);
}

// fp32 -> fp16 (vectorized, 8 elems/thread)
__global__ void split_f32(const float* __restrict__ x, __half* __restrict__ h, int n) {
    int i = (blockIdx.x * 256 + threadIdx.x) * 8;
    if (i >= n) return;
    float4 a = *(const float4*)(x + i);
    float4 b = *(const float4*)(x + i + 4);
    *(uint4*)(h + i) = make_uint4(pack_h2(a.x, a.y), pack_h2(a.z, a.w),
                                  pack_h2(b.x, b.y), pack_h2(b.z, b.w));
}

// ---------------------------------------------------------------------------
// HMMA GEMM: C[M,512] = act(A[M,K] @ W[K,512] + bias)
// A rounded fp16 [M,K]; W rounded fp16 [512][K] (col-major B). 1 MMA pass.
// BM=128, BN=64, BK=64, 4-stage cp.async pipeline, 256 threads (8 warps 4x2),
// warp tile 32x32. Stage = A 16KB | B 8KB = 24 KB. 2 CTAs/SM.
// ---------------------------------------------------------------------------
#define STAGE_BYTES 24576
#define GEMM_SMEM   (4 * STAGE_BYTES)

template <int ACT, int WF32, int WH16>
__global__ void __launch_bounds__(256, 2)
gemm_hmma(const __half* __restrict__ Ah, const __half* __restrict__ Bw,
          const float* __restrict__ bias, float* __restrict__ Cf,
          __half* __restrict__ Ch, int Ktot) {
    extern __shared__ __align__(1024) char smem[];
    const uint32_t sb = smem_u32(smem);
    const int tid = threadIdx.x, wid = tid >> 5, lane = tid & 31;
    const int warp_m = wid & 3, warp_n = wid >> 2;   // 4 x 2
    const int bm = blockIdx.y * 128, bn = blockIdx.x * 64;

    const __half* a0 = Ah + (size_t)bm * Ktot;
    const __half* b0 = Bw + (size_t)bn * Ktot;

    float acc[2][4][4];
#pragma unroll
    for (int a = 0; a < 2; a++)
#pragma unroll
        for (int b = 0; b < 4; b++)
#pragma unroll
            for (int c = 0; c < 4; c++) acc[a][b][c] = 0.f;

    const int a_row = warp_m * 32 + (lane & 15);                          // + mt*16
    const int a_kb  = ((lane >> 4) & 1) * 16;
    const int b_row = warp_n * 32 + ((lane >> 4) & 1) * 8 + (lane & 7);   // + nt2*16
    const int b_kb  = ((lane >> 3) & 1) * 16;

    const int S = Ktot >> 6;   // >= 4 for all our GEMMs

    // 1536 16B-chunks per stage (A:1024, B:512); 6 per thread.
    auto load_stage = [&](int buf, int k0) {
        const uint32_t st = sb + buf * STAGE_BYTES;
#pragma unroll
        for (int i = 0; i < 6; i++) {
            if (i < 4) {
                const int c   = tid + (i << 8);         // 0..1023 -> A
                const int row = c >> 3, kc = c & 7;
                cpasync16(st + swz(row * 128 + kc * 16),
                          a0 + (size_t)row * Ktot + k0 + kc * 8);
            } else {
                const int c   = tid + ((i - 4) << 8);   // 0..511 -> B
                const int row = c >> 3, kc = c & 7;
                cpasync16(st + 16384 + swz(row * 128 + kc * 16),
                          b0 + (size_t)row * Ktot + k0 + kc * 8);
            }
        }
    };

    load_stage(0, 0);   CP_COMMIT();
    load_stage(1, 64);  CP_COMMIT();
    load_stage(2, 128); CP_COMMIT();

    for (int s = 0; s < S; s++) {
        CP_WAIT(2);
        __syncthreads();
        if (s + 3 < S) load_stage((s + 3) & 3, (s + 3) << 6);
        CP_COMMIT();

        const uint32_t tb = sb + (s & 3) * STAGE_BYTES;
#pragma unroll
        for (int kk = 0; kk < 4; kk++) {
            uint32_t ah[8], bh[8];
#pragma unroll
            for (int mt = 0; mt < 2; mt++) {
                const int off = swz((a_row + mt * 16) * 128 + kk * 32 + a_kb);
                ldsm4(ah + 4 * mt, tb + off);
            }
#pragma unroll
            for (int nt2 = 0; nt2 < 2; nt2++) {
                const int off = swz((b_row + nt2 * 16) * 128 + kk * 32 + b_kb);
                ldsm4(bh + 4 * nt2, tb + 16384 + off);
            }
#pragma unroll
            for (int mt = 0; mt < 2; mt++)
#pragma unroll
                for (int nt = 0; nt < 4; nt++)
                    mma16816h(acc[mt][nt], ah + 4 * mt, bh + nt * 2);
        }
        __syncthreads();
    }

    // ---- epilogue: bias + act + store (fp32 and/or fp16) ----
    const int col_base = bn + warp_n * 32 + (lane & 3) * 2;
    const int row_base = bm + warp_m * 32 + (lane >> 2);
#pragma unroll
    for (int nt = 0; nt < 4; nt++) {
        const int col = col_base + nt * 8;
        const float2 bv = *(const float2*)&bias[col];
#pragma unroll
        for (int mt = 0; mt < 2; mt++) {
#pragma unroll
            for (int half_ = 0; half_ < 2; half_++) {
                const int row = row_base + mt * 16 + half_ * 8;
                float v0 = acc[mt][nt][half_ * 2 + 0] + bv.x;
                float v1 = acc[mt][nt][half_ * 2 + 1] + bv.y;
                if (ACT) {
                    v0 = v0 > 0.f ? v0 : expm1f(v0);
                    v1 = v1 > 0.f ? v1 : expm1f(v1);
                }
                if (WF32)
                    *(float2*)(Cf + (size_t)row * 512 + col) = make_float2(v0, v1);
                if (WH16)
                    *(uint32_t*)(Ch + (size_t)row * 512 + col) = pack_h2(v0, v1);
            }
        }
    }
}

// ---------------------------------------------------------------------------
// Fused residual + LayerNorm (+ optional ELU). OUT: fp32 or fp16.
// ---------------------------------------------------------------------------
template <int ACT, int H16>
__global__ void __launch_bounds__(256)
ln_res(const float* __restrict__ a, const float* __restrict__ rr, float rscale,
       const float* __restrict__ g, const float* __restrict__ b,
       float* __restrict__ of, __half* __restrict__ oh) {
    __shared__ float red[8];
    const int row = blockIdx.x, t = threadIdx.x;
    const float* ap = a  + (size_t)row * 512;
    const float* rp = rr + (size_t)row * 512;

    float x0 = ap[t]       + rscale * rp[t];
    float x1 = ap[t + 256] + rscale * rp[t + 256];

    float s = x0 + x1;
#pragma unroll
    for (int o = 16; o > 0; o >>= 1) s += __shfl_xor_sync(0xffffffffu, s, o);
    if ((t & 31) == 0) red[t >> 5] = s;
    __syncthreads();
    float mean = 0.f;
#pragma unroll
    for (int w = 0; w < 8; w++) mean += red[w];
    mean *= (1.0f / 512.0f);
    __syncthreads();

    float d0 = x0 - mean, d1 = x1 - mean;
    float vs = d0 * d0 + d1 * d1;
#pragma unroll
    for (int o = 16; o > 0; o >>= 1) vs += __shfl_xor_sync(0xffffffffu, vs, o);
    if ((t & 31) == 0) red[t >> 5] = vs;
    __syncthreads();
    float var = 0.f;
#pragma unroll
    for (int w = 0; w < 8; w++) var += red[w];
    var *= (1.0f / 512.0f);

    const float inv = rsqrtf(var + LN_EPS);
    float y0 = d0 * inv * g[t]       + b[t];
    float y1 = d1 * inv * g[t + 256] + b[t + 256];
    if (ACT) {
        y0 = y0 > 0.f ? y0 : expm1f(y0);
        y1 = y1 > 0.f ? y1 : expm1f(y1);
    }
    if (H16) {
        oh[(size_t)row * 512 + t]       = __float2half_rn(y0);
        oh[(size_t)row * 512 + t + 256] = __float2half_rn(y1);
    } else {
        of[(size_t)row * 512 + t]       = y0;
        of[(size_t)row * 512 + t + 256] = y1;
    }
}

// ---------------------------------------------------------------------------
// Neighbor attention (one warp per node). fp16 q/k/v in, fp16 out.
// ---------------------------------------------------------------------------
__global__ void __launch_bounds__(256)
nbr_attn(const __half* __restrict__ q, const __half* __restrict__ kc,
         const __half* __restrict__ vc, const int* __restrict__ nbrs,
         __half* __restrict__ oh) {
    const int warp = threadIdx.x >> 5;
    const int lane = threadIdx.x & 31;
    const int node = blockIdx.x * 8 + warp;

    const size_t base = (size_t)node * 512 + lane * 16;
    float qr[16];
    {
        uint4 u0 = *(const uint4*)(q + base);
        uint4 u1 = *(const uint4*)(q + base + 8);
        h8_to_f(u0, qr); h8_to_f(u1, qr + 8);
    }

    float m = -1e30f, s = 0.f;
    float acc[16];
#pragma unroll
    for (int i = 0; i < 16; i++) acc[i] = 0.f;

#pragma unroll
    for (int j = 0; j < KNBR; j++) {
        const int nb = __ldg(&nbrs[node * KNBR + j]);
        const __half* kp = kc + (size_t)nb * 512 + lane * 16;
        const __half* vp = vc + (size_t)nb * 512 + lane * 16;

        float kr[16], vr[16];
        uint4 k0 = *(const uint4*)kp;
        uint4 k1 = *(const uint4*)(kp + 8);
        uint4 v0 = *(const uint4*)vp;
        uint4 v1 = *(const uint4*)(vp + 8);
        h8_to_f(k0, kr); h8_to_f(k1, kr + 8);
        h8_to_f(v0, vr); h8_to_f(v1, vr + 8);

        float dot = 0.f;
#pragma unroll
        for (int i = 0; i < 16; i++) dot = fmaf(kr[i], qr[i], dot);
        dot += __shfl_xor_sync(0xffffffffu, dot, 1);
        dot += __shfl_xor_sync(0xffffffffu, dot, 2);
        const float score = dot * 0.125f;

        const float mn   = fmaxf(m, score);
        const float corr = __expf(m - mn);
        const float p    = __expf(score - mn);
        s = s * corr + p;
#pragma unroll
        for (int i = 0; i < 16; i++) acc[i] = acc[i] * corr + p * vr[i];
        m = mn;
    }

    const float inv = 1.f / s;
    uint32_t ph[8];
#pragma unroll
    for (int j = 0; j < 8; j++)
        ph[j] = pack_h2(acc[2 * j] * inv, acc[2 * j + 1] * inv);
    *(uint4*)(oh + base)     = make_uint4(ph[0], ph[1], ph[2], ph[3]);
    *(uint4*)(oh + base + 8) = make_uint4(ph[4], ph[5], ph[6], ph[7]);
}

// ---------------------------------------------------------------------------
// Launch
// ---------------------------------------------------------------------------
extern "C" void kernel_launch(void* const* d_in, const int* in_sizes, int n_in,
                              void* d_out, int out_size) {
    (void)in_sizes; (void)n_in; (void)out_size;
    const float* data   = (const float*)d_in[0];
    const int*   nbrs   = (const int*)  d_in[1];
    const float* mlp_w0 = (const float*)d_in[2];
    const float* mlp_b0 = (const float*)d_in[3];
    const float* mlp_w1 = (const float*)d_in[4];
    const float* mlp_b1 = (const float*)d_in[5];
    const float* mlp_w2 = (const float*)d_in[6];
    const float* mlp_b2 = (const float*)d_in[7];
    const float* pd_w   = (const float*)d_in[8];
    const float* pd_b   = (const float*)d_in[9];
    const float* pi_w   = (const float*)d_in[10];
    const float* pi_b   = (const float*)d_in[11];
    const float* q_w    = (const float*)d_in[12];
    const float* q_b    = (const float*)d_in[13];
    const float* k_w    = (const float*)d_in[14];
    const float* k_b    = (const float*)d_in[15];
    const float* v_w    = (const float*)d_in[16];
    const float* v_b    = (const float*)d_in[17];
    const float* o_w    = (const float*)d_in[18];
    const float* o_b    = (const float*)d_in[19];
    const float* ln1_g  = (const float*)d_in[20];
    const float* ln1_b  = (const float*)d_in[21];
    const float* ln2_g  = (const float*)d_in[22];
    const float* ln2_b  = (const float*)d_in[23];
    float* out = (float*)d_out;

    __half *data_h, *h1_h, *h2_h, *loc_h, *at_h, *qh, *kh, *vh;
    float *h3, *pd, *inter, *pi;
    __half *w0t, *w1t, *w2t, *pdt, *pit, *qt, *kt, *vt, *ot;
    cudaGetSymbolAddress((void**)&data_h, g_data_h);
    cudaGetSymbolAddress((void**)&h1_h, g_h1_h);
    cudaGetSymbolAddress((void**)&h2_h, g_h2_h);
    cudaGetSymbolAddress((void**)&loc_h, g_loc_h);
    cudaGetSymbolAddress((void**)&at_h, g_at_h);
    cudaGetSymbolAddress((void**)&qh, g_qh);   cudaGetSymbolAddress((void**)&kh, g_kh);
    cudaGetSymbolAddress((void**)&vh, g_vh);
    cudaGetSymbolAddress((void**)&h3, g_h3);   cudaGetSymbolAddress((void**)&pd, g_pd);
    cudaGetSymbolAddress((void**)&inter, g_inter);
    cudaGetSymbolAddress((void**)&pi, g_pi);
    cudaGetSymbolAddress((void**)&w0t, g_w0t); cudaGetSymbolAddress((void**)&w1t, g_w1t);
    cudaGetSymbolAddress((void**)&w2t, g_w2t); cudaGetSymbolAddress((void**)&pdt, g_pdt);
    cudaGetSymbolAddress((void**)&pit, g_pit); cudaGetSymbolAddress((void**)&qt,  g_qt);
    cudaGetSymbolAddress((void**)&kt,  g_kt);  cudaGetSymbolAddress((void**)&vt,  g_vt);
    cudaGetSymbolAddress((void**)&ot,  g_ot);

    cudaFuncSetAttribute(gemm_hmma<1, 0, 1>, cudaFuncAttributeMaxDynamicSharedMemorySize, GEMM_SMEM);
    cudaFuncSetAttribute(gemm_hmma<0, 1, 0>, cudaFuncAttributeMaxDynamicSharedMemorySize, GEMM_SMEM);
    cudaFuncSetAttribute(gemm_hmma<0, 0, 1>, cudaFuncAttributeMaxDynamicSharedMemorySize, GEMM_SMEM);

    WJobs jobs;
    jobs.j[0] = {mlp_w0, w0t, 256};
    jobs.j[1] = {mlp_w1, w1t, 512};
    jobs.j[2] = {mlp_w2, w2t, 512};
    jobs.j[3] = {pd_w,   pdt, 256};
    jobs.j[4] = {pi_w,   pit, 256};
    jobs.j[5] = {q_w,    qt,  512};
    jobs.j[6] = {k_w,    kt,  512};
    jobs.j[7] = {v_w,    vt,  512};
    jobs.j[8] = {o_w,    ot,  512};

    const dim3 gg(8, 128);   // BN=64 -> 8 column tiles

    // 0: all weight transposes (fp16 round)
    wsplit_all<<<dim3(16, 16, 9), dim3(32, 8)>>>(jobs);
    // 1: data -> fp16
    split_f32<<<(NROW * IN_DIM) / (256 * 8), 256>>>(data, data_h, NROW * IN_DIM);
    // 2..5: GEMMs
    gemm_hmma<1, 0, 1><<<gg, 256, GEMM_SMEM>>>(data_h, w0t, mlp_b0, nullptr, h1_h, 256);
    gemm_hmma<1, 0, 1><<<gg, 256, GEMM_SMEM>>>(h1_h,   w1t, mlp_b1, nullptr, h2_h, 512);
    gemm_hmma<0, 1, 0><<<gg, 256, GEMM_SMEM>>>(h2_h,   w2t, mlp_b2, h3, nullptr, 512);
    gemm_hmma<0, 1, 0><<<gg, 256, GEMM_SMEM>>>(data_h, pdt, pd_b,   pd, nullptr, 256);
    // 6: local = elu(LN(h3 + 2*pd)) -> fp16
    ln_res<1, 1><<<NROW, 256>>>(h3, pd, 2.0f, ln1_g, ln1_b, nullptr, loc_h);
    // 7-9: Q, K, V projections -> fp16
    gemm_hmma<0, 0, 1><<<gg, 256, GEMM_SMEM>>>(loc_h, qt, q_b, nullptr, qh, 512);
    gemm_hmma<0, 0, 1><<<gg, 256, GEMM_SMEM>>>(loc_h, kt, k_b, nullptr, kh, 512);
    gemm_hmma<0, 0, 1><<<gg, 256, GEMM_SMEM>>>(loc_h, vt, v_b, nullptr, vh, 512);
    // 10: neighbor attention (fp16 gather) -> fp16
    nbr_attn<<<NROW / 8, 256>>>(qh, kh, vh, nbrs, at_h);
    // 11-12: output projection + project_in
    gemm_hmma<0, 1, 0><<<gg, 256, GEMM_SMEM>>>(at_h,   ot,  o_b,  inter, nullptr, 512);
    gemm_hmma<0, 1, 0><<<gg, 256, GEMM_SMEM>>>(data_h, pit, pi_b, pi,    nullptr, 256);
    // 13: out = LN(inter + pi)
    ln_res<0, 0><<<NROW, 256>>>(inter, pi, 1.0f, ln2_g, ln2_b, out, nullptr);
}